// round 15
// baseline (speedup 1.0000x reference)
#include <cuda_runtime.h>
#include <cuda_bf16.h>
#include <cstdint>

#define BB 8
#define NN 2048
#define DD 64
#define TIM 64               // i-rows per CTA (4 warps x 16)
#define KC 32                // j-chunk
#define NCHUNK (NN / KC)     // 64
#define SPLIT 4
#define CPS (NCHUNK / SPLIT) // 16 chunks per CTA
#define HPITCH 144           // smem H row pitch: conflict-free ldmatrix
#define BPITCH 80            // smem bit-row pitch (64B data + 16B pad)
#define PREP_BLOCKS 512      // 512 x 32 rows = 16384 rows
#define PACK_BLOCKS ((BB * NN * NN / 8) / 256)   // 16384

// ---- dynamic smem layout for attn (bytes) ----
#define HBUF (KC * HPITCH)               // 4608 per buffer
#define SM_BA 0                          // adj bits: 64 rows x 80B = 5120
#define SM_BJ 5120                       // job bits: 5120
#define SM_H  10240                      // [2][HBUF]
#define SM_T  (SM_H + 2 * HBUF)          // [2][128]
#define SM_V  (SM_T + 2 * 128)           // [2][128]
#define SMEM_TOTAL (SM_V + 2 * 128)      // 19968

// ---- device scratch ----
__device__ __nv_bfloat16 g_hb[BB * NN * DD];  // H: [n][d] bf16
__device__ float g_s[BB * NN];
__device__ float g_t[BB * NN];
__device__ float g_u[BB * NN];
__device__ float g_v[BB * NN];
__device__ float g_lam[2 * DD];
// bit-packed masks: [b][i][j/8] -> 4.19 MB each
__device__ uint8_t g_mba[BB * NN * NN / 8];
__device__ uint8_t g_mbj[BB * NN * NN / 8];
// split-K partials
__device__ float g_nA[SPLIT][BB * NN * DD];
__device__ float g_nJ[SPLIT][BB * NN * DD];
__device__ float g_dA[SPLIT][BB * NN];
__device__ float g_dJ[SPLIT][BB * NN];
// per-group arrival counters (zero-initialized at load; reset each launch)
__device__ unsigned int g_cnt[BB * (NN / TIM)];

// ---- PTX helpers (base-target instructions only) ----
__device__ __forceinline__ void mma_bf16(float* d,
    uint32_t a0, uint32_t a1, uint32_t a2, uint32_t a3, uint32_t b0, uint32_t b1) {
    asm volatile(
        "mma.sync.aligned.m16n8k16.row.col.f32.bf16.bf16.f32 "
        "{%0,%1,%2,%3}, {%4,%5,%6,%7}, {%8,%9}, {%0,%1,%2,%3};"
        : "+f"(d[0]), "+f"(d[1]), "+f"(d[2]), "+f"(d[3])
        : "r"(a0), "r"(a1), "r"(a2), "r"(a3), "r"(b0), "r"(b1));
}
__device__ __forceinline__ void ldsm4t(uint32_t& r0, uint32_t& r1, uint32_t& r2, uint32_t& r3, uint32_t addr) {
    asm volatile("ldmatrix.sync.aligned.m8n8.x4.trans.shared.b16 {%0,%1,%2,%3}, [%4];"
        : "=r"(r0), "=r"(r1), "=r"(r2), "=r"(r3) : "r"(addr));
}
__device__ __forceinline__ uint32_t packbf(float lo, float hi) {
    uint32_t r;
    asm("cvt.rn.satfinite.bf16x2.f32 %0, %1, %2;" : "=r"(r) : "f"(hi), "f"(lo));
    return r;
}
#define CP16(dst, src) asm volatile("cp.async.cg.shared.global [%0], [%1], 16;" :: "r"(dst), "l"(src))
#define CP_COMMIT()    asm volatile("cp.async.commit_group;" ::: "memory")
#define CP_WAIT0()     asm volatile("cp.async.wait_group 0;" ::: "memory")

__device__ __forceinline__ float bsel(uint32_t w, int n, float pv) {
    return ((w >> n) & 1u) ? pv : 0.f;
}
// j-permutation: HMMA k-slot kk (0..15) -> global j within 16-block.
__device__ __forceinline__ int psi(int kk) {
    return (((kk >> 1) & 3) << 2) + ((kk >> 3) << 1) + (kk & 1);
}

// =====================================================================
// Kernel P+A fused: blocks [0,512) = prep; rest = bit-pack (DRAM stream)
// =====================================================================
__global__ __launch_bounds__(256) void prep_pack_kernel(
    const int* __restrict__ mask_adj, const int* __restrict__ mask_job,
    const float* __restrict__ feats, const float* __restrict__ W,
    const float* __restrict__ attn_src, const float* __restrict__ attn_dst,
    const float* __restrict__ lambda_params)
{
    __shared__ float sWt[DD * 66];   // sWt[d*66+o] = W[o][d]
    __shared__ float sF[32 * DD];    // 32 rows, row-major

    if (blockIdx.x >= PREP_BLOCKS) {
        // ---- pack branch: pure stream, evict-first loads ----
        const size_t tau = (size_t)(blockIdx.x - PREP_BLOCKS) * 256 + threadIdx.x;
        const int4* pa = (const int4*)mask_adj + tau * 2;
        const int4* pj = (const int4*)mask_job + tau * 2;
        const int4 a0 = __ldcs(pa),     a1 = __ldcs(pa + 1);
        const int4 j0 = __ldcs(pj),     j1 = __ldcs(pj + 1);
        uint32_t ba = (a0.x & 1) | ((a0.y & 1) << 1) | ((a0.z & 1) << 2) | ((a0.w & 1) << 3)
                    | ((a1.x & 1) << 4) | ((a1.y & 1) << 5) | ((a1.z & 1) << 6) | ((a1.w & 1) << 7);
        uint32_t bj = (j0.x & 1) | ((j0.y & 1) << 1) | ((j0.z & 1) << 2) | ((j0.w & 1) << 3)
                    | ((j1.x & 1) << 4) | ((j1.y & 1) << 5) | ((j1.z & 1) << 6) | ((j1.w & 1) << 7);
        g_mba[tau] = (uint8_t)ba;
        g_mbj[tau] = (uint8_t)bj;
        return;
    }

    // ---- prep branch: 256 threads, 32 rows; warp = 4 rows ----
    const int t = threadIdx.x;
    const int warp = t >> 5, lane = t & 31;
    const int o = lane * 2;
    const int row0 = blockIdx.x * 32;
    const int rb = warp * 4;

    #pragma unroll
    for (int w = 0; w < 16; ++w) {
        int x = t + 256 * w;
        sWt[(x & 63) * 66 + (x >> 6)] = W[x];
    }
    #pragma unroll
    for (int w = 0; w < 2; ++w) {
        const int x4 = t + 256 * w;
        *(float4*)&sF[x4 * 4] = *(const float4*)(feats + (size_t)row0 * DD + x4 * 4);
    }
    __syncthreads();

    float h[4][2];
    #pragma unroll
    for (int r = 0; r < 4; ++r) { h[r][0] = 0.f; h[r][1] = 0.f; }

    #pragma unroll
    for (int d = 0; d < DD; ++d) {
        const float2 w2 = *(const float2*)&sWt[d * 66 + o];
        #pragma unroll
        for (int r = 0; r < 4; ++r) {
            const float fd = sF[(rb + r) * DD + d];
            h[r][0] = fmaf(fd, w2.x, h[r][0]);
            h[r][1] = fmaf(fd, w2.y, h[r][1]);
        }
    }

    #pragma unroll
    for (int r = 0; r < 4; ++r) {
        *(__nv_bfloat162*)(g_hb + (size_t)(row0 + rb + r) * DD + o) =
            __nv_bfloat162(__float2bfloat16(h[r][0]), __float2bfloat16(h[r][1]));
    }

    const float2 ws = *(const float2*)(attn_src + o);
    const float2 wd = *(const float2*)(attn_dst + o);
    float rs[4], rd[4];
    #pragma unroll
    for (int r = 0; r < 4; ++r) {
        rs[r] = h[r][0] * ws.x + h[r][1] * ws.y;
        rd[r] = h[r][0] * wd.x + h[r][1] * wd.y;
    }
    #pragma unroll
    for (int off = 16; off; off >>= 1) {
        #pragma unroll
        for (int r = 0; r < 4; ++r) {
            rs[r] += __shfl_down_sync(0xffffffffu, rs[r], off);
            rd[r] += __shfl_down_sync(0xffffffffu, rd[r], off);
        }
    }
    if (lane == 0) {
        #pragma unroll
        for (int r = 0; r < 4; ++r) {
            const int n = row0 + rb + r;
            g_s[n] = expf(rs[r]);
            g_u[n] = expf(0.2f * rs[r]);
            g_t[n] = expf(rd[r]);
            g_v[n] = expf(0.2f * rd[r]);
        }
    }
    if (blockIdx.x == 0 && t >= 64 && t < 128) {
        int d = t - 64;
        float l0 = lambda_params[d * 2];
        float l1 = lambda_params[d * 2 + 1];
        float m = fmaxf(l0, l1);
        float e0 = expf(l0 - m), e1 = expf(l1 - m);
        float inv = 1.0f / (e0 + e1);
        g_lam[d] = e0 * inv;
        g_lam[DD + d] = e1 * inv;
    }
}

// =====================================================================
// Kernel B: HMMA dual-masked attention on bit-packed masks + fused
// last-CTA combine. grid = (32, 8, SPLIT), 128 threads, 4 CTAs/SM.
// =====================================================================
__global__ __launch_bounds__(128, 4) void attn_hmma_kernel(
    const int* __restrict__ bidx,
    const float* __restrict__ feats, float* __restrict__ out)
{
    extern __shared__ __align__(16) char smem[];
    __shared__ int sLast;

    const int t = threadIdx.x;
    const int lane = t & 31, wid = t >> 5;
    const int b = blockIdx.y;
    const int sp = blockIdx.z;
    const int i_base = blockIdx.x * TIM;
    const int bN = b * NN;

    int mb = bidx[b];                 // arange(B) identity gather; clamp defensively
    if (mb < 0 || mb >= BB) mb = b;

    const int g  = lane >> 2;
    const int tq = lane & 3;
    const int r0 = wid * 16 + g;      // tile row 0..63
    const int r1 = r0 + 8;

    const float si0 = g_s[bN + i_base + r0], ui0 = g_u[bN + i_base + r0];
    const float si1 = g_s[bN + i_base + r1], ui1 = g_u[bN + i_base + r1];

    const uint32_t sub = (uint32_t)__cvta_generic_to_shared(smem);

    // ---- preload mask bits: 64 rows x 64B per mask ----
    {
        const int srow = t & 63;
        const int which = t >> 6;     // 0 = adj, 1 = job
        const uint8_t* src = (which ? g_mbj : g_mba)
            + ((size_t)(mb * NN + i_base + srow) << 8) + sp * 64;
        const uint32_t dst = sub + (which ? SM_BJ : SM_BA) + srow * BPITCH;
        CP16(dst,      src);
        CP16(dst + 16, src + 16);
        CP16(dst + 32, src + 32);
        CP16(dst + 48, src + 48);
    }

    // ---- H/t/v staging ----
    const int srow = t >> 1, shalf = t & 1;            // H rows 0..31 for t<64
    const int srowp = (srow & 16) | psi(srow & 15);    // H row permutation
    const char* hSrc = (const char*)(g_hb + ((size_t)(bN + srowp) << 6)) + shalf * 64;
    const uint32_t hDst = sub + SM_H + srow * HPITCH + shalf * 64;

    auto stage = [&](int c, int s) {
        if (t < 64) {   // H: 32 rows x 128B (row-permuted source)
            const char* hp = hSrc + (size_t)c * KC * 128;
            const uint32_t dh = hDst + s * HBUF;
            CP16(dh,      hp);
            CP16(dh + 16, hp + 16);
            CP16(dh + 32, hp + 32);
            CP16(dh + 48, hp + 48);
        } else if (t < 72) {
            CP16(sub + SM_T + s * 128 + (t - 64) * 16, (const char*)(g_t + bN + c * KC) + (t - 64) * 16);
        } else if (t < 80) {
            CP16(sub + SM_V + s * 128 + (t - 72) * 16, (const char*)(g_v + bN + c * KC) + (t - 72) * 16);
        }
    };

    // ldmatrix per-lane offset (smem row = k index)
    const int mid = lane >> 3, mrow = lane & 7;
    const int lmoff = ((mid & 1) * 8 + mrow) * HPITCH + (mid >> 1) * 16;

    float accA[32], accJ[32];
    #pragma unroll
    for (int q = 0; q < 32; ++q) { accA[q] = 0.f; accJ[q] = 0.f; }
    float denA0 = 0.f, denA1 = 0.f, denJ0 = 0.f, denJ1 = 0.f;

    const int c0 = sp * CPS;
    stage(c0, 0);                     // same group as bit preload
    CP_COMMIT();

    const char* bA = smem + SM_BA;
    const char* bJ = smem + SM_BJ;

    for (int ci = 0; ci < CPS; ++ci) {
        const int s = ci & 1;
        CP_WAIT0();
        __syncthreads();              // buffer s visible; prev compute done
        if (ci + 1 < CPS) { stage(c0 + ci + 1, 1 - s); CP_COMMIT(); }

        // mask words for this chunk (broadcast LDS.32)
        const uint32_t wA0 = *(const uint32_t*)(bA + r0 * BPITCH + ci * 4);
        const uint32_t wA1 = *(const uint32_t*)(bA + r1 * BPITCH + ci * 4);
        const uint32_t wJ0 = *(const uint32_t*)(bJ + r0 * BPITCH + ci * 4);
        const uint32_t wJ1 = *(const uint32_t*)(bJ + r1 * BPITCH + ci * 4);

        const uint32_t hbase = sub + SM_H + s * HBUF + lmoff;
        const float* sTs = (const float*)(smem + SM_T + s * 128);
        const float* sVs = (const float*)(smem + SM_V + s * 128);

        #pragma unroll
        for (int kt = 0; kt < 2; ++kt) {
            const float4 t4 = *(const float4*)&sTs[kt * 16 + 4 * tq];
            const float4 v4 = *(const float4*)&sVs[kt * 16 + 4 * tq];

            // exp(leaky(e)) = max(st, uv)
            const float pv00 = fmaxf(si0 * t4.x, ui0 * v4.x);
            const float pv01 = fmaxf(si0 * t4.y, ui0 * v4.y);
            const float pv02 = fmaxf(si0 * t4.z, ui0 * v4.z);
            const float pv03 = fmaxf(si0 * t4.w, ui0 * v4.w);
            const float pv10 = fmaxf(si1 * t4.x, ui1 * v4.x);
            const float pv11 = fmaxf(si1 * t4.y, ui1 * v4.y);
            const float pv12 = fmaxf(si1 * t4.z, ui1 * v4.z);
            const float pv13 = fmaxf(si1 * t4.w, ui1 * v4.w);

            const int n0 = kt * 16 + 4 * tq;
            const float A00 = bsel(wA0, n0 + 0, pv00), A01 = bsel(wA0, n0 + 1, pv01);
            const float A02 = bsel(wA0, n0 + 2, pv02), A03 = bsel(wA0, n0 + 3, pv03);
            const float A10 = bsel(wA1, n0 + 0, pv10), A11 = bsel(wA1, n0 + 1, pv11);
            const float A12 = bsel(wA1, n0 + 2, pv12), A13 = bsel(wA1, n0 + 3, pv13);
            const float J00 = bsel(wJ0, n0 + 0, pv00), J01 = bsel(wJ0, n0 + 1, pv01);
            const float J02 = bsel(wJ0, n0 + 2, pv02), J03 = bsel(wJ0, n0 + 3, pv03);
            const float J10 = bsel(wJ1, n0 + 0, pv10), J11 = bsel(wJ1, n0 + 1, pv11);
            const float J12 = bsel(wJ1, n0 + 2, pv12), J13 = bsel(wJ1, n0 + 3, pv13);

            denA0 += (A00 + A01) + (A02 + A03);
            denA1 += (A10 + A11) + (A12 + A13);
            denJ0 += (J00 + J01) + (J02 + J03);
            denJ1 += (J10 + J11) + (J12 + J13);

            const uint32_t aA0 = packbf(A00, A01), aA1 = packbf(A10, A11);
            const uint32_t aA2 = packbf(A02, A03), aA3 = packbf(A12, A13);
            const uint32_t aJ0 = packbf(J00, J01), aJ1 = packbf(J10, J11);
            const uint32_t aJ2 = packbf(J02, J03), aJ3 = packbf(J12, J13);

            const uint32_t hb = hbase + kt * (16 * HPITCH);
            #pragma unroll
            for (int np = 0; np < 4; ++np) {
                uint32_t b0, b1, b2, b3;
                ldsm4t(b0, b1, b2, b3, hb + np * 32);
                mma_bf16(&accA[(2 * np) * 4],     aA0, aA1, aA2, aA3, b0, b1);
                mma_bf16(&accA[(2 * np + 1) * 4], aA0, aA1, aA2, aA3, b2, b3);
                mma_bf16(&accJ[(2 * np) * 4],     aJ0, aJ1, aJ2, aJ3, b0, b1);
                mma_bf16(&accJ[(2 * np + 1) * 4], aJ0, aJ1, aJ2, aJ3, b2, b3);
            }
        }
    }

    // denominator butterfly over the 4 lanes sharing g
    denA0 += __shfl_xor_sync(0xffffffffu, denA0, 1);
    denA0 += __shfl_xor_sync(0xffffffffu, denA0, 2);
    denA1 += __shfl_xor_sync(0xffffffffu, denA1, 1);
    denA1 += __shfl_xor_sync(0xffffffffu, denA1, 2);
    denJ0 += __shfl_xor_sync(0xffffffffu, denJ0, 1);
    denJ0 += __shfl_xor_sync(0xffffffffu, denJ0, 2);
    denJ1 += __shfl_xor_sync(0xffffffffu, denJ1, 1);
    denJ1 += __shfl_xor_sync(0xffffffffu, denJ1, 2);

    // ---- write partials ----
    float* nA = g_nA[sp];
    float* nJ = g_nJ[sp];
    const size_t o0b = (size_t)(bN + i_base + r0) << 6;
    const size_t o1b = (size_t)(bN + i_base + r1) << 6;
    #pragma unroll
    for (int n = 0; n < 8; ++n) {
        const int cc = n * 8 + 2 * tq;
        *(float2*)(nA + o0b + cc) = make_float2(accA[n * 4 + 0], accA[n * 4 + 1]);
        *(float2*)(nA + o1b + cc) = make_float2(accA[n * 4 + 2], accA[n * 4 + 3]);
        *(float2*)(nJ + o0b + cc) = make_float2(accJ[n * 4 + 0], accJ[n * 4 + 1]);
        *(float2*)(nJ + o1b + cc) = make_float2(accJ[n * 4 + 2], accJ[n * 4 + 3]);
    }
    if (tq == 0) {
        g_dA[sp][bN + i_base + r0] = denA0;
        g_dA[sp][bN + i_base + r1] = denA1;
        g_dJ[sp][bN + i_base + r0] = denJ0;
        g_dJ[sp][bN + i_base + r1] = denJ1;
    }

    // ---- last-CTA combine ----
    __threadfence();                 // partials visible before arrival
    __syncthreads();                 // all threads' stores issued
    const int gid = b * (NN / TIM) + blockIdx.x;
    if (t == 0) {
        const unsigned int old = atomicAdd(&g_cnt[gid], 1u);
        sLast = (old == SPLIT - 1);
        if (sLast) g_cnt[gid] = 0;   // reset for next launch (deterministic)
    }
    __syncthreads();
    if (!sLast) return;
    __threadfence();                 // acquire: other CTAs' partials

    #pragma unroll
    for (int q = 0; q < 8; ++q) {
        const int li = q * 128 + t;          // float4 index 0..1023
        const int row = li >> 4;             // 0..63
        const int dq = (li & 15) * 4;        // d offset 0..60
        const int n = bN + i_base + row;
        const size_t idx = ((size_t)n << 6) + dq;

        float4 na = make_float4(0.f, 0.f, 0.f, 0.f);
        float4 nj = make_float4(0.f, 0.f, 0.f, 0.f);
        float da = 0.f, dj = 0.f;
        #pragma unroll
        for (int s2 = 0; s2 < SPLIT; ++s2) {
            const float4 a = *(const float4*)(g_nA[s2] + idx);
            const float4 j = *(const float4*)(g_nJ[s2] + idx);
            na.x += a.x; na.y += a.y; na.z += a.z; na.w += a.w;
            nj.x += j.x; nj.y += j.y; nj.z += j.z; nj.w += j.w;
            da += g_dA[s2][n];
            dj += g_dJ[s2][n];
        }
        const float ra = 1.0f / da;
        const float rj = 1.0f / dj;
        const float4 lA = *(const float4*)&g_lam[dq];
        const float4 lJ = *(const float4*)&g_lam[DD + dq];
        const float4 f = *(const float4*)(feats + idx);
        float4 o;
        o.x = lA.x * na.x * ra + lJ.x * nj.x * rj + f.x;
        o.y = lA.y * na.y * ra + lJ.y * nj.y * rj + f.y;
        o.z = lA.z * na.z * ra + lJ.z * nj.z * rj + f.z;
        o.w = lA.w * na.w * ra + lJ.w * nj.w * rj + f.w;
        *(float4*)(out + idx) = o;
    }
}

extern "C" void kernel_launch(void* const* d_in, const int* in_sizes, int n_in,
                              void* d_out, int out_size) {
    (void)in_sizes; (void)n_in; (void)out_size;
    const int*   mask_adj      = (const int*)d_in[0];
    const int*   mask_job      = (const int*)d_in[1];
    const int*   bidx          = (const int*)d_in[2];
    const float* feats         = (const float*)d_in[3];
    const float* W             = (const float*)d_in[4];
    const float* attn_src      = (const float*)d_in[5];
    const float* attn_dst      = (const float*)d_in[6];
    const float* lambda_params = (const float*)d_in[7];
    float* out = (float*)d_out;

    prep_pack_kernel<<<PREP_BLOCKS + PACK_BLOCKS, 256>>>(
        mask_adj, mask_job, feats, W, attn_src, attn_dst, lambda_params);
    attn_hmma_kernel<<<dim3(NN / TIM, BB, SPLIT), 128, SMEM_TOTAL>>>(bidx, feats, out);
}

// round 16
// speedup vs baseline: 1.1053x; 1.1053x over previous
#include <cuda_runtime.h>
#include <cuda_bf16.h>
#include <cstdint>

#define BB 8
#define NN 2048
#define DD 64
#define TIM 64               // i-rows per CTA (4 warps x 16)
#define KC 32                // j-chunk
#define NCHUNK (NN / KC)     // 64
#define SPLIT 4
#define CPS (NCHUNK / SPLIT) // 16 chunks per CTA
#define HPITCH 144           // smem H row pitch: conflict-free ldmatrix
#define BPITCH 80            // smem bit-row pitch (64B data + 16B pad)
#define PREP_BLOCKS 512      // 512 x 32 rows = 16384 rows
#define PACK_BLOCKS ((BB * NN * NN / 8) / 256)   // 16384
#define ONES2 0x3F803F80u    // bf16x2 {1.0, 1.0}

// ---- dynamic smem layout for attn (bytes) ----
#define HBUF (KC * HPITCH)               // 4608 per buffer
#define SM_BA 0                          // adj bits: 64 rows x 80B = 5120
#define SM_BJ 5120                       // job bits: 5120
#define SM_H  10240                      // [2][HBUF]
#define SM_T  (SM_H + 2 * HBUF)          // [2][64]  (bf16 t chunk)
#define SM_V  (SM_T + 2 * 64)            // [2][64]
#define SMEM_TOTAL (SM_V + 2 * 64)       // 19712

// ---- device scratch ----
__device__ __nv_bfloat16 g_hb[BB * NN * DD];  // H: [n][d] bf16
__device__ float g_s[BB * NN];
__device__ float g_u[BB * NN];
__device__ __nv_bfloat16 g_tb[BB * NN];       // bf16 exp(a_dst)
__device__ __nv_bfloat16 g_vb[BB * NN];       // bf16 exp(0.2*a_dst)
__device__ float g_lam[2 * DD];
// bit-packed masks: [b][i][j/8] -> 4.19 MB each
__device__ uint8_t g_mba[BB * NN * NN / 8];
__device__ uint8_t g_mbj[BB * NN * NN / 8];
// split-K partials
__device__ float g_nA[SPLIT][BB * NN * DD];
__device__ float g_nJ[SPLIT][BB * NN * DD];
__device__ float g_dA[SPLIT][BB * NN];
__device__ float g_dJ[SPLIT][BB * NN];

// ---- PTX helpers (compute_103-legal: sm_80/90 baseline) ----
__device__ __forceinline__ void mma_bf16(float* d,
    uint32_t a0, uint32_t a1, uint32_t a2, uint32_t a3, uint32_t b0, uint32_t b1) {
    asm volatile(
        "mma.sync.aligned.m16n8k16.row.col.f32.bf16.bf16.f32 "
        "{%0,%1,%2,%3}, {%4,%5,%6,%7}, {%8,%9}, {%0,%1,%2,%3};"
        : "+f"(d[0]), "+f"(d[1]), "+f"(d[2]), "+f"(d[3])
        : "r"(a0), "r"(a1), "r"(a2), "r"(a3), "r"(b0), "r"(b1));
}
__device__ __forceinline__ void ldsm4t(uint32_t& r0, uint32_t& r1, uint32_t& r2, uint32_t& r3, uint32_t addr) {
    asm volatile("ldmatrix.sync.aligned.m8n8.x4.trans.shared.b16 {%0,%1,%2,%3}, [%4];"
        : "=r"(r0), "=r"(r1), "=r"(r2), "=r"(r3) : "r"(addr));
}
__device__ __forceinline__ uint32_t splatbf(float x) {
    uint32_t r;
    asm("cvt.rn.bf16x2.f32 %0, %1, %1;" : "=r"(r) : "f"(x));
    return r;
}
__device__ __forceinline__ uint32_t mul2(uint32_t a, uint32_t b) {
    uint32_t d;
    asm("mul.rn.bf16x2 %0, %1, %2;" : "=r"(d) : "r"(a), "r"(b));
    return d;
}
__device__ __forceinline__ uint32_t max2(uint32_t a, uint32_t b) {
    uint32_t d;
    asm("max.bf16x2 %0, %1, %2;" : "=r"(d) : "r"(a), "r"(b));
    return d;
}
#define CP16(dst, src) asm volatile("cp.async.cg.shared.global [%0], [%1], 16;" :: "r"(dst), "l"(src))
#define CP_COMMIT()    asm volatile("cp.async.commit_group;" ::: "memory")
#define CP_WAIT0()     asm volatile("cp.async.wait_group 0;" ::: "memory")

// j-permutation: HMMA k-slot kk (0..15) -> global j within 16-block.
__device__ __forceinline__ int psi(int kk) {
    return (((kk >> 1) & 3) << 2) + ((kk >> 3) << 1) + (kk & 1);
}

// =====================================================================
// Kernel P+A fused: blocks [0,512) = prep; rest = bit-pack (DRAM stream)
// =====================================================================
__global__ __launch_bounds__(256) void prep_pack_kernel(
    const int* __restrict__ mask_adj, const int* __restrict__ mask_job,
    const float* __restrict__ feats, const float* __restrict__ W,
    const float* __restrict__ attn_src, const float* __restrict__ attn_dst,
    const float* __restrict__ lambda_params)
{
    __shared__ float sWt[DD * 66];   // sWt[d*66+o] = W[o][d]
    __shared__ float sF[32 * DD];    // 32 rows, row-major

    if (blockIdx.x >= PREP_BLOCKS) {
        // ---- pack branch: pure stream, evict-first loads ----
        const size_t tau = (size_t)(blockIdx.x - PREP_BLOCKS) * 256 + threadIdx.x;
        const int4* pa = (const int4*)mask_adj + tau * 2;
        const int4* pj = (const int4*)mask_job + tau * 2;
        const int4 a0 = __ldcs(pa),     a1 = __ldcs(pa + 1);
        const int4 j0 = __ldcs(pj),     j1 = __ldcs(pj + 1);
        uint32_t ba = (a0.x & 1) | ((a0.y & 1) << 1) | ((a0.z & 1) << 2) | ((a0.w & 1) << 3)
                    | ((a1.x & 1) << 4) | ((a1.y & 1) << 5) | ((a1.z & 1) << 6) | ((a1.w & 1) << 7);
        uint32_t bj = (j0.x & 1) | ((j0.y & 1) << 1) | ((j0.z & 1) << 2) | ((j0.w & 1) << 3)
                    | ((j1.x & 1) << 4) | ((j1.y & 1) << 5) | ((j1.z & 1) << 6) | ((j1.w & 1) << 7);
        g_mba[tau] = (uint8_t)ba;
        g_mbj[tau] = (uint8_t)bj;
        return;
    }

    // ---- prep branch: 256 threads, 32 rows; warp = 4 rows ----
    const int t = threadIdx.x;
    const int warp = t >> 5, lane = t & 31;
    const int o = lane * 2;
    const int row0 = blockIdx.x * 32;
    const int rb = warp * 4;

    #pragma unroll
    for (int w = 0; w < 16; ++w) {
        int x = t + 256 * w;
        sWt[(x & 63) * 66 + (x >> 6)] = W[x];
    }
    #pragma unroll
    for (int w = 0; w < 2; ++w) {
        const int x4 = t + 256 * w;
        *(float4*)&sF[x4 * 4] = *(const float4*)(feats + (size_t)row0 * DD + x4 * 4);
    }
    __syncthreads();

    float h[4][2];
    #pragma unroll
    for (int r = 0; r < 4; ++r) { h[r][0] = 0.f; h[r][1] = 0.f; }

    #pragma unroll
    for (int d = 0; d < DD; ++d) {
        const float2 w2 = *(const float2*)&sWt[d * 66 + o];
        #pragma unroll
        for (int r = 0; r < 4; ++r) {
            const float fd = sF[(rb + r) * DD + d];
            h[r][0] = fmaf(fd, w2.x, h[r][0]);
            h[r][1] = fmaf(fd, w2.y, h[r][1]);
        }
    }

    #pragma unroll
    for (int r = 0; r < 4; ++r) {
        *(__nv_bfloat162*)(g_hb + (size_t)(row0 + rb + r) * DD + o) =
            __nv_bfloat162(__float2bfloat16(h[r][0]), __float2bfloat16(h[r][1]));
    }

    const float2 ws = *(const float2*)(attn_src + o);
    const float2 wd = *(const float2*)(attn_dst + o);
    float rs[4], rd[4];
    #pragma unroll
    for (int r = 0; r < 4; ++r) {
        rs[r] = h[r][0] * ws.x + h[r][1] * ws.y;
        rd[r] = h[r][0] * wd.x + h[r][1] * wd.y;
    }
    #pragma unroll
    for (int off = 16; off; off >>= 1) {
        #pragma unroll
        for (int r = 0; r < 4; ++r) {
            rs[r] += __shfl_down_sync(0xffffffffu, rs[r], off);
            rd[r] += __shfl_down_sync(0xffffffffu, rd[r], off);
        }
    }
    if (lane == 0) {
        #pragma unroll
        for (int r = 0; r < 4; ++r) {
            const int n = row0 + rb + r;
            g_s[n] = expf(rs[r]);
            g_u[n] = expf(0.2f * rs[r]);
            g_tb[n] = __float2bfloat16(expf(rd[r]));
            g_vb[n] = __float2bfloat16(expf(0.2f * rd[r]));
        }
    }
    if (blockIdx.x == 0 && t >= 64 && t < 128) {
        int d = t - 64;
        float l0 = lambda_params[d * 2];
        float l1 = lambda_params[d * 2 + 1];
        float m = fmaxf(l0, l1);
        float e0 = expf(l0 - m), e1 = expf(l1 - m);
        float inv = 1.0f / (e0 + e1);
        g_lam[d] = e0 * inv;
        g_lam[DD + d] = e1 * inv;
    }
}

// =====================================================================
// Kernel B: HMMA dual-masked attention on bit-packed masks
// grid = (32, 8, SPLIT), 128 threads, 4 CTAs/SM
// packed-bf16 pv, LUT mask expansion, denominators via ones-MMA
// =====================================================================
__global__ __launch_bounds__(128, 4) void attn_hmma_kernel(const int* __restrict__ bidx)
{
    extern __shared__ __align__(16) char smem[];
    __shared__ uint2 sLut[16];        // nibble -> two half-masks

    const int t = threadIdx.x;
    const int lane = t & 31, wid = t >> 5;
    const int b = blockIdx.y;
    const int sp = blockIdx.z;
    const int i_base = blockIdx.x * TIM;
    const int bN = b * NN;

    int mb = bidx[b];                 // arange(B) identity gather; clamp defensively
    if (mb < 0 || mb >= BB) mb = b;

    if (t < 16) {
        const uint32_t lo = ((t & 1) ? 0x0000FFFFu : 0u) | ((t & 2) ? 0xFFFF0000u : 0u);
        const uint32_t hi = ((t & 4) ? 0x0000FFFFu : 0u) | ((t & 8) ? 0xFFFF0000u : 0u);
        sLut[t] = make_uint2(lo, hi);
    }

    const int g  = lane >> 2;
    const int tq = lane & 3;
    const int r0 = wid * 16 + g;      // tile row 0..63
    const int r1 = r0 + 8;

    const uint32_t si0 = splatbf(g_s[bN + i_base + r0]);
    const uint32_t ui0 = splatbf(g_u[bN + i_base + r0]);
    const uint32_t si1 = splatbf(g_s[bN + i_base + r1]);
    const uint32_t ui1 = splatbf(g_u[bN + i_base + r1]);

    const uint32_t sub = (uint32_t)__cvta_generic_to_shared(smem);

    // ---- preload mask bits: 64 rows x 64B per mask ----
    {
        const int srow = t & 63;
        const int which = t >> 6;     // 0 = adj, 1 = job
        const uint8_t* src = (which ? g_mbj : g_mba)
            + ((size_t)(mb * NN + i_base + srow) << 8) + sp * 64;
        const uint32_t dst = sub + (which ? SM_BJ : SM_BA) + srow * BPITCH;
        CP16(dst,      src);
        CP16(dst + 16, src + 16);
        CP16(dst + 32, src + 32);
        CP16(dst + 48, src + 48);
    }

    // ---- H/t/v staging ----
    const int srow = t >> 1, shalf = t & 1;            // H rows 0..31 for t<64
    const int srowp = (srow & 16) | psi(srow & 15);    // H row permutation
    const char* hSrc = (const char*)(g_hb + ((size_t)(bN + srowp) << 6)) + shalf * 64;
    const uint32_t hDst = sub + SM_H + srow * HPITCH + shalf * 64;

    auto stage = [&](int c, int s) {
        if (t < 64) {   // H: 32 rows x 128B (row-permuted source)
            const char* hp = hSrc + (size_t)c * KC * 128;
            const uint32_t dh = hDst + s * HBUF;
            CP16(dh,      hp);
            CP16(dh + 16, hp + 16);
            CP16(dh + 32, hp + 32);
            CP16(dh + 48, hp + 48);
        } else if (t < 68) {
            CP16(sub + SM_T + s * 64 + (t - 64) * 16, (const char*)(g_tb + bN + c * KC) + (t - 64) * 16);
        } else if (t < 72) {
            CP16(sub + SM_V + s * 64 + (t - 68) * 16, (const char*)(g_vb + bN + c * KC) + (t - 68) * 16);
        }
    };

    // ldmatrix per-lane offset (smem row = k index)
    const int mid = lane >> 3, mrow = lane & 7;
    const int lmoff = ((mid & 1) * 8 + mrow) * HPITCH + (mid >> 1) * 16;

    float accA[32], accJ[32];
    float accDA[4], accDJ[4];
    #pragma unroll
    for (int q = 0; q < 32; ++q) { accA[q] = 0.f; accJ[q] = 0.f; }
    #pragma unroll
    for (int q = 0; q < 4; ++q) { accDA[q] = 0.f; accDJ[q] = 0.f; }

    const int c0 = sp * CPS;
    stage(c0, 0);                     // same group as bit preload
    CP_COMMIT();

    const char* bA = smem + SM_BA;
    const char* bJ = smem + SM_BJ;

    for (int ci = 0; ci < CPS; ++ci) {
        const int s = ci & 1;
        CP_WAIT0();
        __syncthreads();              // buffer s visible; prev compute done (also covers sLut)
        if (ci + 1 < CPS) { stage(c0 + ci + 1, 1 - s); CP_COMMIT(); }

        // mask words for this chunk (broadcast LDS.32)
        const uint32_t wA0 = *(const uint32_t*)(bA + r0 * BPITCH + ci * 4);
        const uint32_t wA1 = *(const uint32_t*)(bA + r1 * BPITCH + ci * 4);
        const uint32_t wJ0 = *(const uint32_t*)(bJ + r0 * BPITCH + ci * 4);
        const uint32_t wJ1 = *(const uint32_t*)(bJ + r1 * BPITCH + ci * 4);

        const uint32_t hbase = sub + SM_H + s * HBUF + lmoff;
        const char* sTb = smem + SM_T + s * 64;
        const char* sVb = smem + SM_V + s * 64;

        #pragma unroll
        for (int kt = 0; kt < 2; ++kt) {
            const int n0 = kt * 16 + 4 * tq;
            const uint2 tp = *(const uint2*)(sTb + kt * 32 + tq * 8);   // t pairs {j0j1, j2j3}
            const uint2 vp = *(const uint2*)(sVb + kt * 32 + tq * 8);

            // pv = max(s*t, u*v), packed bf16x2
            const uint32_t pv01_0 = max2(mul2(si0, tp.x), mul2(ui0, vp.x));
            const uint32_t pv23_0 = max2(mul2(si0, tp.y), mul2(ui0, vp.y));
            const uint32_t pv01_1 = max2(mul2(si1, tp.x), mul2(ui1, vp.x));
            const uint32_t pv23_1 = max2(mul2(si1, tp.y), mul2(ui1, vp.y));

            // mask nibbles -> half-mask words
            const uint2 mA0 = sLut[(wA0 >> n0) & 0xF];
            const uint2 mA1 = sLut[(wA1 >> n0) & 0xF];
            const uint2 mJ0 = sLut[(wJ0 >> n0) & 0xF];
            const uint2 mJ1 = sLut[(wJ1 >> n0) & 0xF];

            const uint32_t aA0 = pv01_0 & mA0.x, aA2 = pv23_0 & mA0.y;
            const uint32_t aA1 = pv01_1 & mA1.x, aA3 = pv23_1 & mA1.y;
            const uint32_t aJ0 = pv01_0 & mJ0.x, aJ2 = pv23_0 & mJ0.y;
            const uint32_t aJ1 = pv01_1 & mJ1.x, aJ3 = pv23_1 & mJ1.y;

            // denominators: row sums via ones-B MMA (no ldsm; all-1.0 fragment)
            mma_bf16(accDA, aA0, aA1, aA2, aA3, ONES2, ONES2);
            mma_bf16(accDJ, aJ0, aJ1, aJ2, aJ3, ONES2, ONES2);

            const uint32_t hb = hbase + kt * (16 * HPITCH);
            #pragma unroll
            for (int np = 0; np < 4; ++np) {
                uint32_t b0, b1, b2, b3;
                ldsm4t(b0, b1, b2, b3, hb + np * 32);
                mma_bf16(&accA[(2 * np) * 4],     aA0, aA1, aA2, aA3, b0, b1);
                mma_bf16(&accA[(2 * np + 1) * 4], aA0, aA1, aA2, aA3, b2, b3);
                mma_bf16(&accJ[(2 * np) * 4],     aJ0, aJ1, aJ2, aJ3, b0, b1);
                mma_bf16(&accJ[(2 * np + 1) * 4], aJ0, aJ1, aJ2, aJ3, b2, b3);
            }
        }
    }

    // ---- write partials (denominators from ones-MMA accumulators) ----
    float* nA = g_nA[sp];
    float* nJ = g_nJ[sp];
    const size_t o0b = (size_t)(bN + i_base + r0) << 6;
    const size_t o1b = (size_t)(bN + i_base + r1) << 6;
    #pragma unroll
    for (int n = 0; n < 8; ++n) {
        const int cc = n * 8 + 2 * tq;
        *(float2*)(nA + o0b + cc) = make_float2(accA[n * 4 + 0], accA[n * 4 + 1]);
        *(float2*)(nA + o1b + cc) = make_float2(accA[n * 4 + 2], accA[n * 4 + 3]);
        *(float2*)(nJ + o0b + cc) = make_float2(accJ[n * 4 + 0], accJ[n * 4 + 1]);
        *(float2*)(nJ + o1b + cc) = make_float2(accJ[n * 4 + 2], accJ[n * 4 + 3]);
    }
    if (tq == 0) {
        g_dA[sp][bN + i_base + r0] = accDA[0];
        g_dA[sp][bN + i_base + r1] = accDA[2];
        g_dJ[sp][bN + i_base + r0] = accDJ[0];
        g_dJ[sp][bN + i_base + r1] = accDJ[2];
    }
}

// =====================================================================
// Kernel C: combine splits, normalize, blend, residual
// =====================================================================
__global__ __launch_bounds__(256) void combine_kernel(
    const float* __restrict__ feats, float* __restrict__ out)
{
    const int idx = (blockIdx.x * blockDim.x + threadIdx.x) * 4;
    const int n = idx >> 6;
    const int d = idx & 63;

    float4 na = make_float4(0.f, 0.f, 0.f, 0.f);
    float4 nj = make_float4(0.f, 0.f, 0.f, 0.f);
    float da = 0.f, dj = 0.f;
    #pragma unroll
    for (int sp = 0; sp < SPLIT; ++sp) {
        const float4 a = *(const float4*)(g_nA[sp] + idx);
        const float4 j = *(const float4*)(g_nJ[sp] + idx);
        na.x += a.x; na.y += a.y; na.z += a.z; na.w += a.w;
        nj.x += j.x; nj.y += j.y; nj.z += j.z; nj.w += j.w;
        da += g_dA[sp][n];
        dj += g_dJ[sp][n];
    }
    const float ra = 1.0f / da;
    const float rj = 1.0f / dj;
    const float4 lA = *(const float4*)&g_lam[d];
    const float4 lJ = *(const float4*)&g_lam[DD + d];
    const float4 f = *(const float4*)(feats + idx);
    float4 o;
    o.x = lA.x * na.x * ra + lJ.x * nj.x * rj + f.x;
    o.y = lA.y * na.y * ra + lJ.y * nj.y * rj + f.y;
    o.z = lA.z * na.z * ra + lJ.z * nj.z * rj + f.z;
    o.w = lA.w * na.w * ra + lJ.w * nj.w * rj + f.w;
    *(float4*)(out + idx) = o;
}

extern "C" void kernel_launch(void* const* d_in, const int* in_sizes, int n_in,
                              void* d_out, int out_size) {
    (void)in_sizes; (void)n_in; (void)out_size;
    const int*   mask_adj      = (const int*)d_in[0];
    const int*   mask_job      = (const int*)d_in[1];
    const int*   bidx          = (const int*)d_in[2];
    const float* feats         = (const float*)d_in[3];
    const float* W             = (const float*)d_in[4];
    const float* attn_src      = (const float*)d_in[5];
    const float* attn_dst      = (const float*)d_in[6];
    const float* lambda_params = (const float*)d_in[7];
    float* out = (float*)d_out;

    prep_pack_kernel<<<PREP_BLOCKS + PACK_BLOCKS, 256>>>(
        mask_adj, mask_job, feats, W, attn_src, attn_dst, lambda_params);
    attn_hmma_kernel<<<dim3(NN / TIM, BB, SPLIT), 128, SMEM_TOTAL>>>(bidx);
    combine_kernel<<<BB * NN * DD / 4 / 256, 256>>>(feats, out);
}